// round 16
// baseline (speedup 1.0000x reference)
#include <cuda_runtime.h>

#define BB 8
#define GG 64
#define PP 32768
#define NC 80
#define NCHUNK 128           // sorted pred chunks (256 preds each)
#define NBIN 1024

// all scratch fully overwritten (or self-resetting) every run -> graph-safe.
__device__ unsigned long long g_partial[BB * NCHUNK * GG];
__device__ unsigned long long g_final[BB * GG];
__device__ float4 g_rec[BB * PP * 2];   // per-(b,orig p): {W,Scx,Scy,Slw},{Slh,gth,ign,0}
__device__ unsigned g_hist[NBIN];       // zero-init; reset by scan each run
__device__ unsigned g_cursor[NBIN];     // rebuilt each run by scan
__device__ unsigned g_done;             // zero-init; self-resetting counter
__device__ float4 g_spc[PP];            // cx-sorted pred corners (px1,px2,py1,py2)
__device__ float  g_spa[PP];            // sorted pred areas
__device__ int    g_sop[PP];            // sorted slot -> original p

// K0: histogram of pred cx into 1024 bins; last block scans -> g_cursor
// (exclusive prefix) and resets g_hist. grid 32 x 256 (4 preds/thread).
__global__ void hist_kernel(const float* __restrict__ pr) {
    __shared__ unsigned sh[NBIN];
    __shared__ unsigned sblk[256];
    __shared__ unsigned s_last;
    int tid = threadIdx.x;
    for (int i = tid; i < NBIN; i += 256) sh[i] = 0;
    __syncthreads();
    int p0 = blockIdx.x * 1024 + tid;
#pragma unroll
    for (int j = 0; j < 4; j++) {
        float cx = ((const float4*)pr)[p0 + j * 256].x;
        int bin = (int)(cx * NBIN);
        bin = bin < 0 ? 0 : (bin > NBIN - 1 ? NBIN - 1 : bin);
        atomicAdd(&sh[bin], 1u);
    }
    __syncthreads();
    for (int i = tid; i < NBIN; i += 256)
        if (sh[i]) atomicAdd(&g_hist[i], sh[i]);
    __threadfence();
    __syncthreads();
    if (tid == 0) {
        unsigned v = atomicAdd(&g_done, 1u);
        s_last = (v == 31) ? 1u : 0u;
        if (v == 31) g_done = 0;                       // replay-safe reset
    }
    __syncthreads();
    if (s_last) {
        __shared__ unsigned sv[NBIN];
        for (int i = tid; i < NBIN; i += 256) { sv[i] = g_hist[i]; g_hist[i] = 0; }
        __syncthreads();
        unsigned loc[4], sum = 0;
#pragma unroll
        for (int k = 0; k < 4; k++) { loc[k] = sum; sum += sv[tid * 4 + k]; }
        sblk[tid] = sum;
        __syncthreads();
        for (int off = 1; off < 256; off <<= 1) {      // Hillis-Steele inclusive
            unsigned v = (tid >= off) ? sblk[tid - off] : 0;
            __syncthreads();
            sblk[tid] += v;
            __syncthreads();
        }
        unsigned base = (tid > 0) ? sblk[tid - 1] : 0;
#pragma unroll
        for (int k = 0; k < 4; k++) g_cursor[tid * 4 + k] = base + loc[k];
    }
}

// K1: scatter preds into cx-sorted order (order within a bin is arbitrary;
// all downstream tie-breaks use the carried original index). grid 128 x 256.
__global__ void scatter_kernel(const float* __restrict__ pr) {
    int p = blockIdx.x * 256 + threadIdx.x;
    float4 v = ((const float4*)pr)[p];                 // pr_boxes[0] per reference
    int bin = (int)(v.x * NBIN);
    bin = bin < 0 ? 0 : (bin > NBIN - 1 ? NBIN - 1 : bin);
    unsigned pos = atomicAdd(&g_cursor[bin], 1u);
    g_spc[pos] = make_float4(v.x - v.z * 0.5f, v.x + v.z * 0.5f,
                             v.y - v.w * 0.5f, v.y + v.w * 0.5f);
    g_spa[pos] = v.z * v.w;
    g_sop[pos] = p;
}

// Kernel A: block = (batch, sorted-chunk). Warp owns 8 gts sequentially; the
// chunk's exact corner range lets a warp SKIP gts with provably-zero overlap
// (~65% of (gt,chunk) scans incl. invalid gts). Active scan: 32 lanes x 8
// preds, exact IEEE q = inter/den in reference association order -> argmax
// keys and q>=0.5 / q>=0.4 decisions are BIT-EXACT with the reference.
// Events drained via rare smem atomics; zero-fills this block's cls slice.
__global__ void __launch_bounds__(256) fused_kernel(const float* __restrict__ gt,
                                                    const float* __restrict__ pr,
                                                    float* __restrict__ out) {
    __shared__ float4 s_pc[256];
    __shared__ float  s_pa[256];
    __shared__ int    s_op[256];
    __shared__ float  s_W[256], s_cx[256], s_cy[256], s_lw[256], s_lh[256];
    __shared__ int    s_gth[256], s_ign[256];
    __shared__ float  s_ggx1[GG], s_ggx2[GG], s_ggy1[GG], s_ggy2[GG], s_gga[GG];
    __shared__ float  s_gcx[GG], s_gcy[GG], s_glw[GG], s_glh[GG];
    __shared__ int    s_minx1, s_maxx2;

    int tid = threadIdx.x;
    int b = blockIdx.x >> 7;
    int chunk = blockIdx.x & (NCHUNK - 1);
    int sbase = chunk * 256;

    if (tid == 0) { s_minx1 = 0x7F7FFFFF; s_maxx2 = 0; }
    s_W[tid] = 0.f; s_cx[tid] = 0.f; s_cy[tid] = 0.f;
    s_lw[tid] = 0.f; s_lh[tid] = 0.f;
    s_gth[tid] = -1; s_ign[tid] = 0;

    {   // zero-fill this block's cls slice (streaming stores drain under compute)
        float4* zc = (float4*)out + (size_t)blockIdx.x * 5120;
        float4 z = make_float4(0.f, 0.f, 0.f, 0.f);
#pragma unroll
        for (int i = 0; i < 20; i++) __stcs(&zc[i * 256 + tid], z);
    }
    __syncthreads();

    {   // stage sorted preds + exact chunk x-range (+1 keeps floats positive
        // for int-bit atomics; RN monotonicity keeps the skip test conservative)
        float4 v = g_spc[sbase + tid];
        s_pc[tid] = v;
        s_pa[tid] = g_spa[sbase + tid];
        s_op[tid] = g_sop[sbase + tid];
        atomicMin(&s_minx1, __float_as_int(v.x + 1.0f));
        atomicMax(&s_maxx2, __float_as_int(v.y + 1.0f));
    }
    if (tid < GG) {   // stage gts (invalid rows auto-skip via inverted corners)
        const float* grow = gt + (b * GG + tid) * 6;
        float cx = grow[0], cy = grow[1], gw = grow[2], gh = grow[3];
        s_ggx1[tid] = cx - gw * 0.5f; s_ggx2[tid] = cx + gw * 0.5f;
        s_ggy1[tid] = cy - gh * 0.5f; s_ggy2[tid] = cy + gh * 0.5f;
        s_gga[tid] = gw * gh;
        s_gcx[tid] = cx; s_gcy[tid] = cy;
        bool valid = (cx != -1.0f);
        s_glw[tid] = valid ? logf(gw) : 0.f;
        s_glh[tid] = valid ? logf(gh) : 0.f;
    }
    __syncthreads();

    float flo = __int_as_float(s_minx1);   // min(px1)+1 over chunk
    float fhi = __int_as_float(s_maxx2);   // max(px2)+1 over chunk
    int wid = tid >> 5, lane = tid & 31;

    int   myop[8];
    float mypa[8];
#pragma unroll
    for (int k = 0; k < 8; k++) {          // lane's preds, reused across 8 gts
        myop[k] = s_op[lane + k * 32];
        mypa[k] = s_pa[lane + k * 32];
    }

    for (int j = 0; j < 8; j++) {
        int g = wid * 8 + j;
        float gx1 = s_ggx1[g], gx2 = s_ggx2[g];
        // skip: provably zero x-overlap with every pred in this chunk
        // (invalid gts: gx2+1 = -0.5 < flo -> always skipped)
        if ((gx2 + 1.0f) < flo || (gx1 + 1.0f) > fhi) {
            if (lane == 0) g_partial[(size_t)blockIdx.x * GG + g] = 0ULL;
            continue;
        }
        float gy1 = s_ggy1[g], gy2 = s_ggy2[g], ga = s_gga[g];

        unsigned long long key = 0ULL;
        unsigned evm = 0;
#pragma unroll
        for (int k = 0; k < 8; k++) {
            float4 c = s_pc[lane + k * 32];
            float iw = fmaxf(0.f, fminf(gx2, c.y) - fmaxf(gx1, c.x));
            float ih = fmaxf(0.f, fminf(gy2, c.w) - fmaxf(gy1, c.z));
            float inter = iw * ih;
            float den = ((ga + mypa[k]) - inter) + 1e-5f;   // reference order
            float q = inter / den;                          // exact IEEE div
            unsigned long long cand =
                ((unsigned long long)__float_as_uint(q) << 32) |
                (unsigned)(0xFFFFFFFFu - (unsigned)myop[k]);
            key = cand > key ? cand : key;                  // max q, then min p
            evm |= (q >= 0.4f) ? (1u << k) : 0u;            // th u ignore events
        }
#pragma unroll
        for (int o = 16; o > 0; o >>= 1) {                  // warp max-reduce
            unsigned long long other = __shfl_xor_sync(0xFFFFFFFFu, key, o);
            key = other > key ? other : key;
        }
        if (lane == 0) g_partial[(size_t)blockIdx.x * GG + g] = key;

        if (evm) {                                          // rare event drain
            float gcx = s_gcx[g], gcy = s_gcy[g];
            float lw = s_glw[g], lh = s_glh[g];
            do {
                int k = __ffs(evm) - 1; evm &= evm - 1;
                int slot = lane + k * 32;
                float4 c = s_pc[slot];
                float iw = fmaxf(0.f, fminf(gx2, c.y) - fmaxf(gx1, c.x));
                float ih = fmaxf(0.f, fminf(gy2, c.w) - fmaxf(gy1, c.z));
                float inter = iw * ih;
                float den = ((ga + mypa[k]) - inter) + 1e-5f;
                float q = inter / den;
                if (q >= 0.5f) {                            // canonical thresh
                    atomicAdd(&s_W[slot], 1.f);
                    atomicAdd(&s_cx[slot], gcx);
                    atomicAdd(&s_cy[slot], gcy);
                    atomicAdd(&s_lw[slot], lw);
                    atomicAdd(&s_lh[slot], lh);
                    atomicMax(&s_gth[slot], g);
                } else {                                    // q in [0.4, 0.5)
                    s_ign[slot] = 1;                        // benign race
                }
            } while (evm);
        }
    }
    __syncthreads();

    {   // per-pred records, scattered to ORIGINAL pred index (32B stores)
        int orig = s_op[tid];
        size_t idx = (size_t)b * PP + orig;
        g_rec[idx * 2]     = make_float4(s_W[tid], s_cx[tid], s_cy[tid], s_lw[tid]);
        g_rec[idx * 2 + 1] = make_float4(s_lh[tid], __int_as_float(s_gth[tid]),
                                         __int_as_float(s_ign[tid]), 0.f);
    }
}

// Kernel A2: reduce 128 chunk-partials -> one key per (b, g). grid 8 x 256.
__global__ void reduce_kernel() {
    __shared__ unsigned long long s_red[256];
    int tid = threadIdx.x;
    int b = blockIdx.x;
    int g = tid & 63, qd = tid >> 6;
    unsigned long long k = 0ULL;
    const unsigned long long* src = g_partial + ((size_t)b * NCHUNK + qd * 32) * GG + g;
#pragma unroll
    for (int i = 0; i < 32; i++) {
        unsigned long long v = src[(size_t)i * GG];
        k = v > k ? v : k;
    }
    s_red[tid] = k;
    __syncthreads();
    if (tid < GG) {
        unsigned long long k0 = s_red[tid],       k1 = s_red[tid + 64];
        unsigned long long k2 = s_red[tid + 128], k3 = s_red[tid + 192];
        unsigned long long a = k0 > k1 ? k0 : k1;
        unsigned long long c = k2 > k3 ? k2 : k3;
        g_final[b * GG + tid] = a > c ? a : c;
    }
}

// Kernel B: merge best-pair term + finalize. grid (128, 8).
// Decode rule: key with q-bits == 0 means max iou over ALL preds is 0 ->
// reference argmax returns 0.
__global__ void __launch_bounds__(256) finalize_kernel(const float* __restrict__ gt,
                                                       const float* __restrict__ pr,
                                                       float* __restrict__ out) {
    __shared__ float s_bw[256], s_bx[256], s_by[256], s_blw[256], s_blh[256];
    __shared__ int   s_bg[256];
    __shared__ float s_lab[GG];

    int tid = threadIdx.x;
    int b = blockIdx.y;
    int p = blockIdx.x * 256 + tid;
    size_t idx = (size_t)b * PP + p;

    // long-latency loads first; consumed after the staging barrier
    float4 r0 = __ldcs(&g_rec[idx * 2]);
    float4 r1 = __ldcs(&g_rec[idx * 2 + 1]);
    float4 pv = ((const float4*)pr)[p];

    s_bw[tid] = 0.f; s_bx[tid] = 0.f; s_by[tid] = 0.f;
    s_blw[tid] = 0.f; s_blh[tid] = 0.f; s_bg[tid] = -1;

    if (tid < GG) {
        const float* grow = gt + (b * GG + tid) * 6;
        float cx = grow[0];
        s_lab[tid] = grow[4];
        bool valid = (cx != -1.0f);
        float conf = grow[5];
        if (valid && conf > 0.f) {
            unsigned long long k = g_final[b * GG + tid];
            int bp = ((unsigned)(k >> 32) == 0u)
                     ? 0
                     : (int)(0xFFFFFFFFu - (unsigned)(k & 0xFFFFFFFFull));
            if ((bp >> 8) == (int)blockIdx.x) {     // best pred lives in this block
                int lp = bp & 255;
                atomicAdd(&s_bw[lp], 1.f);
                atomicAdd(&s_bx[lp], cx);
                atomicAdd(&s_by[lp], grow[1]);
                atomicAdd(&s_blw[lp], logf(grow[2]));
                atomicAdd(&s_blh[lp], logf(grow[3]));
                atomicMax(&s_bg[lp], tid);          // original gt index (monotone)
            }
        }
    }
    __syncthreads();

    float W   = r0.x + s_bw[tid];
    float Scx = r0.y + s_bx[tid];
    float Scy = r0.z + s_by[tid];
    float Slw = r0.w + s_blw[tid];
    float Slh = r1.x + s_blh[tid];
    int gth = __float_as_int(r1.y);
    bool ign = __float_as_int(r1.z) != 0;
    int gbe = s_bg[tid];

    int win = (gbe >= 0) ? gbe : gth;
    bool matched = (win >= 0);
    float mask = matched ? 0.f : 1.f;
    if (ign) mask = -1.f;

    float4 loc;
    if (W > 0.f) {
        loc = make_float4((Scx - W * pv.x) / pv.z,
                          (Scy - W * pv.y) / pv.w,
                          Slw - W * logf(pv.z),
                          Slh - W * logf(pv.w));
    } else {
        loc = make_float4(0.f, 0.f, 0.f, 0.f);      // exact: sums are 0 when W==0
    }

    float* out_loc  = out + (size_t)BB * PP * NC;
    float* out_mask = out + (size_t)BB * PP * (NC + 4);
    ((float4*)out_loc)[idx] = loc;
    out_mask[idx] = mask;

    if (matched) {                                  // sparse one-hot scatter
        int cid = (int)s_lab[win];
        out[idx * NC + cid] = 1.0f;
    }
}

extern "C" void kernel_launch(void* const* d_in, const int* in_sizes, int n_in,
                              void* d_out, int out_size) {
    const float* gt = (const float*)d_in[0];   // [8,64,6]
    const float* pr = (const float*)d_in[1];   // [8,32768,4]
    float* out = (float*)d_out;                // cls ++ loc ++ mask

    hist_kernel<<<32, 256>>>(pr);
    scatter_kernel<<<NCHUNK, 256>>>(pr);
    fused_kernel<<<BB * NCHUNK, 256>>>(gt, pr, out);
    reduce_kernel<<<BB, 256>>>();
    dim3 gridB(PP / 256, BB);
    finalize_kernel<<<gridB, 256>>>(gt, pr, out);
}

// round 17
// speedup vs baseline: 1.7506x; 1.7506x over previous
#include <cuda_runtime.h>

#define BB 8
#define GG 64
#define PP 32768
#define NC 80
#define NCHUNK 128           // pred chunks per batch (256 preds each)

// per-(batch, chunk) partial argmax keys: (q_bits << 32) | (0xFFFFFFFF - p)
// all scratch fully overwritten every run -> no init needed, graph-safe.
__device__ unsigned long long g_partial[BB * NCHUNK * GG];
__device__ unsigned long long g_final[BB * GG];
__device__ float4 g_rec[BB * PP * 2];   // per-(b,p): {W,Scx,Scy,Slw},{Slh,gth,ign,0}

// Kernel A: one pass over all (g, p) pairs of this block's 256 preds.
// Thread = (gt g = tid&63, r = tid>>6) scanning 64 preds in 2 independent
// argmax sub-chains (cross-mult compare, FSEL updates, sticky 1e-6 near-tie
// band resolved by exact-division rescan -> ordering == reference rounded-
// quotient argmax). Threshold/ignore candidates pass ONE coarse in-loop
// filter (inter >= 0.39*den); the rare drain re-tests with canonical forms
// (0.5f/0.4f). cls zero-fill uses streaming stores (__stcs) so the 84MB
// stream does not evict g_rec/pr from L2 before finalize reads them.
__global__ void __launch_bounds__(256) fused_kernel(const float* __restrict__ gt,
                                                    const float* __restrict__ pr,
                                                    float* __restrict__ out) {
    __shared__ float4 s_pc[256];    // px1, px2, py1, py2
    __shared__ float  s_pa[256];
    __shared__ float  s_W[256], s_cx[256], s_cy[256], s_lw[256], s_lh[256];
    __shared__ int    s_gth[256], s_ign[256];
    __shared__ unsigned long long s_key[256];

    int tid = threadIdx.x;
    int b = blockIdx.x >> 7;
    int chunk = blockIdx.x & (NCHUNK - 1);
    int pbase = chunk * 256;

    {   // stage preds
        float4 v = ((const float4*)pr)[pbase + tid];   // pr_boxes[0] per reference
        s_pc[tid] = make_float4(v.x - v.z * 0.5f, v.x + v.z * 0.5f,
                                v.y - v.w * 0.5f, v.y + v.w * 0.5f);
        s_pa[tid] = v.z * v.w;
    }
    s_W[tid] = 0.f; s_cx[tid] = 0.f; s_cy[tid] = 0.f;
    s_lw[tid] = 0.f; s_lh[tid] = 0.f;
    s_gth[tid] = -1; s_ign[tid] = 0;

    {   // zero-fill this block's cls slice with STREAMING stores (evict-first)
        float4* zc = (float4*)out + (size_t)blockIdx.x * 5120;
        float4 z = make_float4(0.f, 0.f, 0.f, 0.f);
#pragma unroll
        for (int i = 0; i < 20; i++) __stcs(&zc[i * 256 + tid], z);
    }

    int g = tid & 63, r = tid >> 6;
    const float* grow = gt + (b * GG + g) * 6;
    float cx = grow[0], cy = grow[1], gw = grow[2], gh = grow[3];
    bool valid = (cx != -1.0f);
    float gx1 = cx - gw * 0.5f, gx2 = cx + gw * 0.5f;
    float gy1 = cy - gh * 0.5f, gy2 = cy + gh * 0.5f;
    float gaeps = gw * gh + 1e-5f;
    // invalid gt (cx=-1): inverted corners -> iw/ih clamp to 0, inter=0,
    // den>0, so events stay false and the argmax key is gated by 'valid'.
    __syncthreads();

    int base = r * 64;
    float bn0 = 0.f, bd0 = 1.f; int bp0 = base;        // chain 0: preds base+0..31
    float bn1 = 0.f, bd1 = 1.f; int bp1 = base + 32;   // chain 1: preds base+32..63
    unsigned m0 = 0, m1 = 0;
    bool band = false;

#pragma unroll 8
    for (int i = 0; i < 32; i++) {
        unsigned bit = 1u << i;
        {   // chain 0
            float4 c = s_pc[base + i];
            float pa = s_pa[base + i];
            float iw = fmaxf(0.f, fminf(gx2, c.y) - fmaxf(gx1, c.x));
            float ih = fmaxf(0.f, fminf(gy2, c.w) - fmaxf(gy1, c.z));
            float inter = iw * ih;
            float den = (gaeps + pa) - inter;
            float a = inter * bd0, cc = bn0 * den;
            bool acc = a > cc;
            float d = a - cc;
            band = band || ((d != 0.f) && (fabsf(d) <= cc * 1e-6f));
            bn0 = acc ? inter : bn0;
            bd0 = acc ? den : bd0;
            bp0 = acc ? base + i : bp0;
            m0 |= (inter >= 0.39f * den) ? bit : 0u;   // coarse event filter
        }
        {   // chain 1
            float4 c = s_pc[base + 32 + i];
            float pa = s_pa[base + 32 + i];
            float iw = fmaxf(0.f, fminf(gx2, c.y) - fmaxf(gx1, c.x));
            float ih = fmaxf(0.f, fminf(gy2, c.w) - fmaxf(gy1, c.z));
            float inter = iw * ih;
            float den = (gaeps + pa) - inter;
            float a = inter * bd1, cc = bn1 * den;
            bool acc = a > cc;
            float d = a - cc;
            band = band || ((d != 0.f) && (fabsf(d) <= cc * 1e-6f));
            bn1 = acc ? inter : bn1;
            bd1 = acc ? den : bd1;
            bp1 = acc ? base + 32 + i : bp1;
            m1 |= (inter >= 0.39f * den) ? bit : 0u;   // coarse event filter
        }
    }
    {   // merge chains (chain 0 holds lower indices -> keep on tie)
        float a = bn1 * bd0, cc = bn0 * bd1;
        bool acc = a > cc;
        float d = a - cc;
        band = band || ((d != 0.f) && (fabsf(d) <= cc * 1e-6f));
        if (acc) { bn0 = bn1; bd0 = bd1; bp0 = bp1; }
    }
    // near-tie fallback: exact rounded-quotient rescan (essentially never taken)
    if (__any_sync(0xFFFFFFFFu, band)) {
        if (band) {
            float bq = 0.f; int bpx = base;
            for (int i = 0; i < 64; i++) {
                float4 c = s_pc[base + i];
                float pa = s_pa[base + i];
                float iw = fmaxf(0.f, fminf(gx2, c.y) - fmaxf(gx1, c.x));
                float ih = fmaxf(0.f, fminf(gy2, c.w) - fmaxf(gy1, c.z));
                float inter = iw * ih;
                float den = (gaeps + pa) - inter;
                float qq = inter / den;
                if (qq > bq) { bq = qq; bpx = base + i; }
            }
            bn0 = bq; bd0 = 1.f; bp0 = bpx;
        }
    }
    float q = bn0 / bd0;               // one exact div -> reference-rounded key
    s_key[tid] = valid
        ? (((unsigned long long)__float_as_uint(q) << 32) |
           (unsigned)(0xFFFFFFFFu - (unsigned)(pbase + bp0)))
        : 0ULL;

    // drain rare candidate events; re-test with the canonical threshold forms
    unsigned long long evm = ((unsigned long long)m1 << 32) | m0;
    if (!valid) evm = 0ULL;
    if (evm) {
        float lw = logf(gw), lh = logf(gh);
        do {
            int i = __ffsll(evm) - 1; evm &= evm - 1;
            int pp = base + i;
            float4 c = s_pc[pp];
            float pa = s_pa[pp];
            float iw = fmaxf(0.f, fminf(gx2, c.y) - fmaxf(gx1, c.x));
            float ih = fmaxf(0.f, fminf(gy2, c.w) - fmaxf(gy1, c.z));
            float inter = iw * ih;
            float den = (gaeps + pa) - inter;
            if (inter >= 0.5f * den) {              // th (canonical form)
                atomicAdd(&s_W[pp], 1.f);
                atomicAdd(&s_cx[pp], cx);
                atomicAdd(&s_cy[pp], cy);
                atomicAdd(&s_lw[pp], lw);
                atomicAdd(&s_lh[pp], lh);
                atomicMax(&s_gth[pp], g);
            } else if (inter >= 0.4f * den) {       // ignore band (canonical)
                s_ign[pp] = 1;                      // benign race: all store 1
            }
        } while (evm);
    }
    __syncthreads();

    if (tid < GG) {                     // per-(block, gt) argmax partial
        unsigned long long k0 = s_key[tid],       k1 = s_key[tid + 64];
        unsigned long long k2 = s_key[tid + 128], k3 = s_key[tid + 192];
        unsigned long long k = k0 > k1 ? k0 : k1;
        unsigned long long m = k2 > k3 ? k2 : k3;
        k = k > m ? k : m;
        g_partial[(size_t)blockIdx.x * GG + tid] = k;
    }

    size_t idx = (size_t)b * PP + pbase + tid;      // per-pred record
    g_rec[idx * 2]     = make_float4(s_W[tid], s_cx[tid], s_cy[tid], s_lw[tid]);
    g_rec[idx * 2 + 1] = make_float4(s_lh[tid], __int_as_float(s_gth[tid]),
                                     __int_as_float(s_ign[tid]), 0.f);
}

// Kernel A2: reduce 128 chunk-partials -> one key per (b, g).
// grid 8 x 1024: 4x the thread parallelism of the old version, 8 loads per
// thread (vs 32) -> memory latency hidden by warp count, serial max chain 4x
// shorter. Two-step smem tree finishes the job.
__global__ void __launch_bounds__(1024) reduce_kernel() {
    __shared__ unsigned long long s_red[1024];
    int tid = threadIdx.x;
    int b = blockIdx.x;
    int g = tid & 63, grp = tid >> 6;            // 16 groups of 8 chunks
    unsigned long long k = 0ULL;
    const unsigned long long* src = g_partial + ((size_t)b * NCHUNK + grp * 8) * GG + g;
#pragma unroll
    for (int i = 0; i < 8; i++) {
        unsigned long long v = src[(size_t)i * GG];
        k = v > k ? v : k;
    }
    s_red[tid] = k;
    __syncthreads();
    if (tid < 256) {
        unsigned long long k0 = s_red[tid],       k1 = s_red[tid + 256];
        unsigned long long k2 = s_red[tid + 512], k3 = s_red[tid + 768];
        unsigned long long a = k0 > k1 ? k0 : k1;
        unsigned long long c = k2 > k3 ? k2 : k3;
        s_red[tid] = a > c ? a : c;
    }
    __syncthreads();
    if (tid < GG) {
        unsigned long long k0 = s_red[tid],       k1 = s_red[tid + 64];
        unsigned long long k2 = s_red[tid + 128], k3 = s_red[tid + 192];
        unsigned long long a = k0 > k1 ? k0 : k1;
        unsigned long long c = k2 > k3 ? k2 : k3;
        g_final[b * GG + tid] = a > c ? a : c;
    }
}

// Kernel B: merge best-pair term + finalize. grid (128, 8).
// g_rec / pr loads are issued at kernel entry (before staging + barrier) so
// their latency is covered by the staging phase; __ldcs = read-once hint.
__global__ void __launch_bounds__(256) finalize_kernel(const float* __restrict__ gt,
                                                       const float* __restrict__ pr,
                                                       float* __restrict__ out) {
    __shared__ float s_bw[256], s_bx[256], s_by[256], s_blw[256], s_blh[256];
    __shared__ int   s_bg[256];
    __shared__ float s_lab[GG];

    int tid = threadIdx.x;
    int b = blockIdx.y;
    int p = blockIdx.x * 256 + tid;
    size_t idx = (size_t)b * PP + p;

    // issue long-latency loads FIRST; consumed after the staging barrier
    float4 r0 = __ldcs(&g_rec[idx * 2]);
    float4 r1 = __ldcs(&g_rec[idx * 2 + 1]);
    float4 pv = ((const float4*)pr)[p];

    s_bw[tid] = 0.f; s_bx[tid] = 0.f; s_by[tid] = 0.f;
    s_blw[tid] = 0.f; s_blh[tid] = 0.f; s_bg[tid] = -1;

    if (tid < GG) {
        const float* grow = gt + (b * GG + tid) * 6;
        float cx = grow[0];
        s_lab[tid] = grow[4];
        bool valid = (cx != -1.0f);
        float conf = grow[5];
        if (valid && conf > 0.f) {
            unsigned long long k = g_final[b * GG + tid];
            int bp = (int)(0xFFFFFFFFu - (unsigned)(k & 0xFFFFFFFFull));
            if ((bp >> 8) == (int)blockIdx.x) {     // best pred lives in this block
                int lp = bp & 255;
                atomicAdd(&s_bw[lp], 1.f);
                atomicAdd(&s_bx[lp], cx);
                atomicAdd(&s_by[lp], grow[1]);
                atomicAdd(&s_blw[lp], logf(grow[2]));
                atomicAdd(&s_blh[lp], logf(grow[3]));
                atomicMax(&s_bg[lp], tid);          // original gt index (monotone)
            }
        }
    }
    __syncthreads();

    float W   = r0.x + s_bw[tid];
    float Scx = r0.y + s_bx[tid];
    float Scy = r0.z + s_by[tid];
    float Slw = r0.w + s_blw[tid];
    float Slh = r1.x + s_blh[tid];
    int gth = __float_as_int(r1.y);
    bool ign = __float_as_int(r1.z) != 0;
    int gbe = s_bg[tid];

    int win = (gbe >= 0) ? gbe : gth;
    bool matched = (win >= 0);
    float mask = matched ? 0.f : 1.f;
    if (ign) mask = -1.f;

    float4 loc;
    if (W > 0.f) {
        loc = make_float4((Scx - W * pv.x) / pv.z,
                          (Scy - W * pv.y) / pv.w,
                          Slw - W * logf(pv.z),
                          Slh - W * logf(pv.w));
    } else {
        loc = make_float4(0.f, 0.f, 0.f, 0.f);      // exact: sums are 0 when W==0
    }

    float* out_loc  = out + (size_t)BB * PP * NC;
    float* out_mask = out + (size_t)BB * PP * (NC + 4);
    ((float4*)out_loc)[idx] = loc;
    out_mask[idx] = mask;

    if (matched) {                                  // sparse one-hot scatter
        int cid = (int)s_lab[win];
        out[idx * NC + cid] = 1.0f;
    }
}

extern "C" void kernel_launch(void* const* d_in, const int* in_sizes, int n_in,
                              void* d_out, int out_size) {
    const float* gt = (const float*)d_in[0];   // [8,64,6]
    const float* pr = (const float*)d_in[1];   // [8,32768,4]
    float* out = (float*)d_out;                // cls ++ loc ++ mask

    fused_kernel<<<BB * NCHUNK, 256>>>(gt, pr, out);
    reduce_kernel<<<BB, 1024>>>();
    dim3 gridB(PP / 256, BB);
    finalize_kernel<<<gridB, 256>>>(gt, pr, out);
}